// round 2
// baseline (speedup 1.0000x reference)
#include <cuda_runtime.h>
#include <math.h>

// Problem dims (fixed for this dataset)
constexpr int S_  = 256;
constexpr int B_  = 8;
constexpr int T_  = 1024;
constexpr int D_  = 512;
constexpr int TS_ = 512;
constexpr int V_  = 32000;
constexpr int SB  = S_ * B_;   // 2048
constexpr int TB  = T_ * B_;   // 8192

// ---------------------------------------------------------------------------
// Scratch: one static __device__ arena (no allocations allowed).
// ---------------------------------------------------------------------------
constexpr size_t OQ  = 0;                      // q / later x      : SB*D
constexpr size_t OK_ = OQ  + (size_t)SB * D_;  // k                : TB*D
constexpr size_t OV  = OK_ + (size_t)TB * D_;  // v                : TB*D
constexpr size_t OA  = OV  + (size_t)TB * D_;  // attn (scores)    : SB*T
constexpr size_t OC  = OA  + (size_t)SB * T_;  // ctx              : SB*D
constexpr size_t OL  = OC  + (size_t)SB * D_;  // layernorm out    : SB*D
constexpr size_t OT  = OL  + (size_t)SB * D_;  // outs_token       : SB*D
constexpr size_t OG  = OT  + (size_t)SB * D_;  // gates            : SB*2
constexpr size_t OM  = OG  + (size_t)SB * 2;   // per-row coef     : SB
constexpr size_t SCRATCH_FLOATS = OM + SB;

__device__ float g_scratch[SCRATCH_FLOATS];

// ---------------------------------------------------------------------------
// Generic NT GEMM: C[m,n] = ACT( alpha * ( sum_k A[m,k]*B[n,k] + bias[n] ) )
// A: M x K (lda), B: N x K (ldb), C: M x N (ldc). blockIdx.z batches via
// sA/sB/sC element strides. BM=BN=128, BK=16, 256 threads, 8x8 per thread.
// ---------------------------------------------------------------------------
template <int ACT>
__global__ __launch_bounds__(256)
void gemm_nt_kernel(const float* __restrict__ A, const float* __restrict__ Bm,
                    const float* __restrict__ bias, float* __restrict__ C,
                    int K, int lda, int ldb, int ldc,
                    long sA, long sB, long sC, float alpha)
{
    A  += (long)blockIdx.z * sA;
    Bm += (long)blockIdx.z * sB;
    C  += (long)blockIdx.z * sC;

    __shared__ float As[16][132];
    __shared__ float Bs[16][132];

    const int t  = threadIdx.x;
    const int tx = t & 15;
    const int ty = t >> 4;
    const long m0 = (long)blockIdx.y * 128;
    const long n0 = (long)blockIdx.x * 128;

    float acc[8][8];
#pragma unroll
    for (int i = 0; i < 8; i++)
#pragma unroll
        for (int j = 0; j < 8; j++) acc[i][j] = 0.f;

    for (int k0 = 0; k0 < K; k0 += 16) {
#pragma unroll
        for (int i = 0; i < 2; i++) {
            int slot = t + i * 256;          // 0..511
            int row  = slot >> 2;            // 0..127
            int kv   = (slot & 3) << 2;      // 0,4,8,12
            float4 av = *(const float4*)(A  + (m0 + row) * lda + k0 + kv);
            As[kv+0][row] = av.x; As[kv+1][row] = av.y;
            As[kv+2][row] = av.z; As[kv+3][row] = av.w;
            float4 bv = *(const float4*)(Bm + (n0 + row) * ldb + k0 + kv);
            Bs[kv+0][row] = bv.x; Bs[kv+1][row] = bv.y;
            Bs[kv+2][row] = bv.z; Bs[kv+3][row] = bv.w;
        }
        __syncthreads();
#pragma unroll
        for (int k = 0; k < 16; k++) {
            float a[8], b[8];
            *(float4*)(a)     = *(const float4*)&As[k][ty * 8];
            *(float4*)(a + 4) = *(const float4*)&As[k][ty * 8 + 4];
            *(float4*)(b)     = *(const float4*)&Bs[k][tx * 8];
            *(float4*)(b + 4) = *(const float4*)&Bs[k][tx * 8 + 4];
#pragma unroll
            for (int i = 0; i < 8; i++)
#pragma unroll
                for (int j = 0; j < 8; j++)
                    acc[i][j] = fmaf(a[i], b[j], acc[i][j]);
        }
        __syncthreads();
    }

#pragma unroll
    for (int i = 0; i < 8; i++) {
        long row = m0 + ty * 8 + i;
        float* crow = C + row * (long)ldc + n0 + tx * 8;
#pragma unroll
        for (int jj = 0; jj < 2; jj++) {
            float vv[4];
#pragma unroll
            for (int j = 0; j < 4; j++) {
                float r = acc[i][jj * 4 + j];
                if (bias) r += bias[n0 + tx * 8 + jj * 4 + j];
                r *= alpha;
                if (ACT == 1) r = tanhf(r);
                vv[j] = r;
            }
            *(float4*)(crow + jj * 4) = make_float4(vv[0], vv[1], vv[2], vv[3]);
        }
    }
}

// ---------------------------------------------------------------------------
// NN GEMM (batched): C[m,n] = sum_k A[m,k] * B[k,n].  Used for ctx = attn @ v.
// ---------------------------------------------------------------------------
__global__ __launch_bounds__(256)
void gemm_nn_kernel(const float* __restrict__ A, const float* __restrict__ Bm,
                    float* __restrict__ C,
                    int K, int lda, int ldb, int ldc,
                    long sA, long sB, long sC)
{
    A  += (long)blockIdx.z * sA;
    Bm += (long)blockIdx.z * sB;
    C  += (long)blockIdx.z * sC;

    __shared__ float As[16][132];
    __shared__ float Bs[16][132];

    const int t  = threadIdx.x;
    const int tx = t & 15;
    const int ty = t >> 4;
    const long m0 = (long)blockIdx.y * 128;
    const long n0 = (long)blockIdx.x * 128;

    float acc[8][8];
#pragma unroll
    for (int i = 0; i < 8; i++)
#pragma unroll
        for (int j = 0; j < 8; j++) acc[i][j] = 0.f;

    for (int k0 = 0; k0 < K; k0 += 16) {
#pragma unroll
        for (int i = 0; i < 2; i++) {
            int slot = t + i * 256;
            // A tile (transpose into SMEM)
            int row = slot >> 2;
            int kv  = (slot & 3) << 2;
            float4 av = *(const float4*)(A + (m0 + row) * lda + k0 + kv);
            As[kv+0][row] = av.x; As[kv+1][row] = av.y;
            As[kv+2][row] = av.z; As[kv+3][row] = av.w;
            // B tile (direct): 16 k-rows x 128 n-cols
            int kk = slot >> 5;            // 0..15
            int nv = (slot & 31) << 2;     // 0..124
            float4 bv = *(const float4*)(Bm + (long)(k0 + kk) * ldb + n0 + nv);
            *(float4*)&Bs[kk][nv] = bv;
        }
        __syncthreads();
#pragma unroll
        for (int k = 0; k < 16; k++) {
            float a[8], b[8];
            *(float4*)(a)     = *(const float4*)&As[k][ty * 8];
            *(float4*)(a + 4) = *(const float4*)&As[k][ty * 8 + 4];
            *(float4*)(b)     = *(const float4*)&Bs[k][tx * 8];
            *(float4*)(b + 4) = *(const float4*)&Bs[k][tx * 8 + 4];
#pragma unroll
            for (int i = 0; i < 8; i++)
#pragma unroll
                for (int j = 0; j < 8; j++)
                    acc[i][j] = fmaf(a[i], b[j], acc[i][j]);
        }
        __syncthreads();
    }

#pragma unroll
    for (int i = 0; i < 8; i++) {
        long row = m0 + ty * 8 + i;
        float* crow = C + row * (long)ldc + n0 + tx * 8;
        *(float4*)(crow)     = make_float4(acc[i][0], acc[i][1], acc[i][2], acc[i][3]);
        *(float4*)(crow + 4) = make_float4(acc[i][4], acc[i][5], acc[i][6], acc[i][7]);
    }
}

// ---------------------------------------------------------------------------
// Softmax over T for attention rows (in-place on scores). mask: [B,T] bytes.
// One block (256 thr) per (s,b) row, T=1024.
// ---------------------------------------------------------------------------
__global__ __launch_bounds__(256)
void attn_softmax_kernel(float* __restrict__ attn, const unsigned char* __restrict__ mask)
{
    int row = blockIdx.x;
    int b   = row & (B_ - 1);
    float* p = attn + (long)row * T_;
    const unsigned char* mrow = mask + (long)b * T_;
    int t = threadIdx.x;
    __shared__ float red[256];

    float x[4];
    float mx = -1e30f;
#pragma unroll
    for (int i = 0; i < 4; i++) {
        int tt = t + i * 256;
        float v = p[tt];
        if (mrow[tt]) v = -1e9f;
        x[i] = v;
        mx = fmaxf(mx, v);
    }
    red[t] = mx; __syncthreads();
    for (int s = 128; s > 0; s >>= 1) {
        if (t < s) red[t] = fmaxf(red[t], red[t + s]);
        __syncthreads();
    }
    mx = red[0]; __syncthreads();

    float sum = 0.f;
#pragma unroll
    for (int i = 0; i < 4; i++) { x[i] = __expf(x[i] - mx); sum += x[i]; }
    red[t] = sum; __syncthreads();
    for (int s = 128; s > 0; s >>= 1) {
        if (t < s) red[t] += red[t + s];
        __syncthreads();
    }
    float inv = 1.f / red[0];
#pragma unroll
    for (int i = 0; i < 4; i++) p[t + i * 256] = x[i] * inv;
}

// ---------------------------------------------------------------------------
// LayerNorm(outs + x) with gain/bias. One block (256 thr) per row, D=512.
// ---------------------------------------------------------------------------
__global__ __launch_bounds__(256)
void ln_kernel(const float* __restrict__ outs, const float* __restrict__ x,
               const float* __restrict__ g, const float* __restrict__ bb,
               float* __restrict__ out)
{
    int row = blockIdx.x;
    int t = threadIdx.x;
    const float* o  = outs + (long)row * D_;
    const float* xr = x    + (long)row * D_;
    __shared__ float red[256];

    float v0 = o[t] + xr[t];
    float v1 = o[t + 256] + xr[t + 256];

    red[t] = v0 + v1; __syncthreads();
    for (int s = 128; s > 0; s >>= 1) { if (t < s) red[t] += red[t + s]; __syncthreads(); }
    float mu = red[0] * (1.f / D_); __syncthreads();

    float d0 = v0 - mu, d1 = v1 - mu;
    red[t] = d0 * d0 + d1 * d1; __syncthreads();
    for (int s = 128; s > 0; s >>= 1) { if (t < s) red[t] += red[t + s]; __syncthreads(); }
    float inv = rsqrtf(red[0] * (1.f / D_) + 1e-5f);

    out[(long)row * D_ + t]       = d0 * inv * g[t]       + bb[t];
    out[(long)row * D_ + t + 256] = d1 * inv * g[t + 256] + bb[t + 256];
}

// ---------------------------------------------------------------------------
// 2-way gate: softmax(tok @ Wdiv^T + bdiv). One block (128 thr) per row.
// ---------------------------------------------------------------------------
__global__ __launch_bounds__(128)
void gates_kernel(const float* __restrict__ tok, const float* __restrict__ Wdiv,
                  const float* __restrict__ bdiv, float* __restrict__ gates)
{
    int row = blockIdx.x;
    int t = threadIdx.x;
    const float* x = tok + (long)row * D_;
    float z0 = 0.f, z1 = 0.f;
    for (int d = t; d < D_; d += 128) {
        float xv = x[d];
        z0 = fmaf(xv, Wdiv[d],      z0);
        z1 = fmaf(xv, Wdiv[D_ + d], z1);
    }
    __shared__ float r0[128], r1[128];
    r0[t] = z0; r1[t] = z1; __syncthreads();
    for (int s = 64; s > 0; s >>= 1) {
        if (t < s) { r0[t] += r0[t + s]; r1[t] += r1[t + s]; }
        __syncthreads();
    }
    if (t == 0) {
        float a = r0[0] + bdiv[0], b = r1[0] + bdiv[1];
        float m = fmaxf(a, b);
        float e0 = __expf(a - m), e1 = __expf(b - m);
        float inv = 1.f / (e0 + e1);
        gates[row * 2 + 0] = e0 * inv;
        gates[row * 2 + 1] = e1 * inv;
    }
}

// ---------------------------------------------------------------------------
// Online softmax stats over V per row; emits c = log(gen) - log(sum) - max.
// One block (256 thr) per row.
// ---------------------------------------------------------------------------
__global__ __launch_bounds__(256)
void rowstats_kernel(const float* __restrict__ logits,
                     const float* __restrict__ gates, float* __restrict__ coef)
{
    int row = blockIdx.x;
    int t = threadIdx.x;
    const float* z = logits + (long)row * V_;
    float m = -1e30f, s = 0.f;
    for (int j = t; j < V_; j += 256) {
        float v = z[j];
        if (v > m) { s = s * __expf(m - v) + 1.f; m = v; }
        else       { s += __expf(v - m); }
    }
    __shared__ float sm[256], ss[256];
    sm[t] = m; ss[t] = s; __syncthreads();
    for (int k = 128; k > 0; k >>= 1) {
        if (t < k) {
            float m1 = sm[t], s1 = ss[t], m2 = sm[t + k], s2 = ss[t + k];
            float M = fmaxf(m1, m2);
            sm[t] = M;
            ss[t] = s1 * __expf(m1 - M) + s2 * __expf(m2 - M);
        }
        __syncthreads();
    }
    if (t == 0)
        coef[row] = __logf(gates[row * 2 + 0]) - __logf(ss[0]) - sm[0];
}

// ---------------------------------------------------------------------------
// Log-prob base pass: out = coef[row] + z  (== log(gen*softmax(z)); no MUFU).
// float4, V divisible by 4. 64000 blocks x 256 threads.
// ---------------------------------------------------------------------------
__global__ __launch_bounds__(256)
void lp_kernel(float* __restrict__ out, const float* __restrict__ coef)
{
    long i4 = (long)blockIdx.x * 256 + threadIdx.x;  // float4 index
    int row = (int)(i4 / (V_ / 4));
    float c = __ldg(coef + row);
    float4* p = (float4*)out + i4;
    float4 v = *p;
    v.x += c; v.y += c; v.z += c; v.w += c;
    *p = v;
}

// ---------------------------------------------------------------------------
// Copy-scatter in log space: ll <- log(exp(ll) + copy_gate*attn) via CAS loop.
// One thread per (row, t): 2048*1024 threads.
// ---------------------------------------------------------------------------
__global__ __launch_bounds__(256)
void scatter_kernel(float* __restrict__ out, const float* __restrict__ attn,
                    const float* __restrict__ gates, const int* __restrict__ copy_seq)
{
    int gid = blockIdx.x * 256 + threadIdx.x;
    int row = gid >> 10;
    int t   = gid & 1023;
    int b   = row & (B_ - 1);
    float val = gates[row * 2 + 1] * attn[(long)row * T_ + t];
    int idx = copy_seq[t * B_ + b];
    int* ia = (int*)(out + (long)row * V_ + idx);

    int assumed = *ia;
    int old;
    do {
        old = assumed;
        float cur = __int_as_float(old);
        float nv = __logf(__expf(cur) + val);
        assumed = atomicCAS(ia, old, __float_as_int(nv));   // FIX: was __int_as_float(nv)
    } while (assumed != old);
}

// ---------------------------------------------------------------------------
// Launch
// ---------------------------------------------------------------------------
extern "C" void kernel_launch(void* const* d_in, const int* in_sizes, int n_in,
                              void* d_out, int out_size)
{
    const float* outs = (const float*)d_in[0];
    const float* gs   = (const float*)d_in[1];
    const unsigned char* mask = (const unsigned char*)d_in[2];
    const int*   cseq = (const int*)d_in[3];
    const float* Wq = (const float*)d_in[4],  *bq = (const float*)d_in[5];
    const float* Wk = (const float*)d_in[6],  *bk = (const float*)d_in[7];
    const float* Wv = (const float*)d_in[8],  *bv = (const float*)d_in[9];
    const float* Wo = (const float*)d_in[10], *bo = (const float*)d_in[11];
    const float* lng = (const float*)d_in[12], *lnb = (const float*)d_in[13];
    const float* Wt = (const float*)d_in[14], *bt = (const float*)d_in[15];
    const float* Wgen = (const float*)d_in[16], *bgen = (const float*)d_in[17];
    const float* Wdiv = (const float*)d_in[18], *bdiv = (const float*)d_in[19];
    float* out = (float*)d_out;

    float* sc = nullptr;
    cudaGetSymbolAddress((void**)&sc, g_scratch);
    float* q    = sc + OQ;   // also reused as x after attention
    float* k    = sc + OK_;
    float* v    = sc + OV;
    float* attn = sc + OA;
    float* ctx  = sc + OC;
    float* ln   = sc + OL;
    float* tok  = sc + OT;
    float* gts  = sc + OG;
    float* coef = sc + OM;

    const float scale = 0.044194173824159216f; // 1/sqrt(512)
    dim3 blk(256);

    // q = (outs @ Wq^T + bq) * scale       [2048 x 512]
    gemm_nt_kernel<0><<<dim3(4, 16, 1), blk>>>(outs, Wq, bq, q, D_, D_, D_, D_, 0, 0, 0, scale);
    // k = gs @ Wk^T + bk                   [8192 x 512]
    gemm_nt_kernel<0><<<dim3(4, 64, 1), blk>>>(gs, Wk, bk, k, D_, D_, D_, D_, 0, 0, 0, 1.f);
    // v = gs @ Wv^T + bv
    gemm_nt_kernel<0><<<dim3(4, 64, 1), blk>>>(gs, Wv, bv, v, D_, D_, D_, D_, 0, 0, 0, 1.f);
    // scores[s,b,t] = q[s,b,:] . k[t,b,:]  (batched over b)
    gemm_nt_kernel<0><<<dim3(8, 2, 8), blk>>>(q, k, nullptr, attn,
                                              D_, B_ * D_, B_ * D_, B_ * T_,
                                              D_, D_, T_, 1.f);
    // softmax over t (with mask)
    attn_softmax_kernel<<<SB, 256>>>(attn, mask);
    // ctx[s,b,:] = attn[s,b,:] @ v[:,b,:]
    gemm_nn_kernel<<<dim3(4, 2, 8), blk>>>(attn, v, ctx,
                                           T_, B_ * T_, B_ * D_, B_ * D_,
                                           T_, D_, D_);
    // x = ctx @ Wo^T + bo   -> reuse q buffer
    gemm_nt_kernel<0><<<dim3(4, 16, 1), blk>>>(ctx, Wo, bo, q, D_, D_, D_, D_, 0, 0, 0, 1.f);
    // outs_ln = LN(outs + x)
    ln_kernel<<<SB, 256>>>(outs, q, lng, lnb, ln);
    // tok = tanh(outs_ln @ Wt^T + bt)
    gemm_nt_kernel<1><<<dim3(4, 16, 1), blk>>>(ln, Wt, bt, tok, D_, D_, D_, TS_, 0, 0, 0, 1.f);
    // gates
    gates_kernel<<<SB, 128>>>(tok, Wdiv, bdiv, gts);
    // logits = tok @ Wgen^T + bgen  -> d_out   [2048 x 32000]
    gemm_nt_kernel<0><<<dim3(250, 16, 1), blk>>>(tok, Wgen, bgen, out, D_, TS_, TS_, V_, 0, 0, 0, 1.f);
    // per-row softmax stats -> coef = log(gen) - log(sum) - max
    rowstats_kernel<<<SB, 256>>>(out, gts, coef);
    // base log-probs in place
    lp_kernel<<<(SB * (V_ / 4)) / 256, 256>>>(out, coef);
    // copy scatter (log-space CAS merge)
    scatter_kernel<<<(SB * T_) / 256, 256>>>(out, attn, gts, cseq);
}

// round 3
// speedup vs baseline: 3.3296x; 3.3296x over previous
#include <cuda_runtime.h>
#include <math.h>
#include <stdint.h>

// Problem dims (fixed for this dataset)
constexpr int S_  = 256;
constexpr int B_  = 8;
constexpr int T_  = 1024;
constexpr int D_  = 512;
constexpr int TS_ = 512;
constexpr int V_  = 32000;
constexpr int SB  = S_ * B_;   // 2048
constexpr int TB  = T_ * B_;   // 8192

// ---------------------------------------------------------------------------
// Scratch arena
// ---------------------------------------------------------------------------
constexpr size_t OQ  = 0;                      // q / later x      : SB*D
constexpr size_t OK_ = OQ  + (size_t)SB * D_;  // k                : TB*D
constexpr size_t OV  = OK_ + (size_t)TB * D_;  // v                : TB*D
constexpr size_t OA  = OV  + (size_t)TB * D_;  // attn (scores)    : SB*T
constexpr size_t OC  = OA  + (size_t)SB * T_;  // ctx              : SB*D
constexpr size_t OL  = OC  + (size_t)SB * D_;  // layernorm out    : SB*D
constexpr size_t OT  = OL  + (size_t)SB * D_;  // outs_token       : SB*D
constexpr size_t OG  = OT  + (size_t)SB * D_;  // gates            : SB*2
constexpr size_t OM  = OG  + (size_t)SB * 2;   // per-row coef     : SB
constexpr size_t SCRATCH_FLOATS = OM + SB;

__device__ float g_scratch[SCRATCH_FLOATS];

// ---------------------------------------------------------------------------
// tf32 helpers
// ---------------------------------------------------------------------------
__device__ __forceinline__ unsigned tf32u(float x) {
    unsigned r;
    asm("cvt.rna.tf32.f32 %0, %1;" : "=r"(r) : "f"(x));
    return r;
}

__device__ __forceinline__ void mma_tf32(float& c0, float& c1, float& c2, float& c3,
                                         unsigned a0, unsigned a1, unsigned a2, unsigned a3,
                                         unsigned b0, unsigned b1)
{
    asm volatile(
        "mma.sync.aligned.m16n8k8.row.col.f32.tf32.tf32.f32 "
        "{%0,%1,%2,%3}, {%4,%5,%6,%7}, {%8,%9}, {%0,%1,%2,%3};"
        : "+f"(c0), "+f"(c1), "+f"(c2), "+f"(c3)
        : "r"(a0), "r"(a1), "r"(a2), "r"(a3), "r"(b0), "r"(b1));
}

// ---------------------------------------------------------------------------
// Tensor-core NT GEMM (tf32): C[m,n] = ACT(alpha*(sum_k A[m,k]*B[n,k] + bias[n]))
// BM=BN=128, BK=32. 256 threads = 8 warps, warp tile 64(M) x 32(N).
// blockIdx.z batches via sA/sB/sC element strides. All dims tile-divisible.
// SMEM pad 36 words/row: fragment-load bank = (4*grp + qid) mod 32 -> conflict-free.
// ---------------------------------------------------------------------------
template <int ACT>
__global__ __launch_bounds__(256)
void mma_nt_kernel(const float* __restrict__ A, const float* __restrict__ Bm,
                   const float* __restrict__ bias, float* __restrict__ C,
                   int K, int lda, int ldb, int ldc,
                   long sA, long sB, long sC, float alpha)
{
    A  += (long)blockIdx.z * sA;
    Bm += (long)blockIdx.z * sB;
    C  += (long)blockIdx.z * sC;

    constexpr int PAD = 36;                 // words per 32-wide row
    __shared__ unsigned As[128 * PAD];
    __shared__ unsigned Bs[128 * PAD];

    const int t    = threadIdx.x;
    const int lane = t & 31;
    const int warp = t >> 5;
    const int wm   = (warp >> 2) * 64;      // 0 or 64
    const int wn   = (warp & 3) * 32;       // 0,32,64,96
    const int grp  = lane >> 2;             // 0..7
    const int qid  = lane & 3;              // 0..3

    const long m0 = (long)blockIdx.y * 128;
    const long n0 = (long)blockIdx.x * 128;

    float acc[4][4][4];
#pragma unroll
    for (int mi = 0; mi < 4; mi++)
#pragma unroll
        for (int ni = 0; ni < 4; ni++)
#pragma unroll
            for (int c = 0; c < 4; c++) acc[mi][ni][c] = 0.f;

    // global->smem thread mapping: 1024 float4 per tile, 4 per thread
    int row_g[4], c4_g[4];
#pragma unroll
    for (int i = 0; i < 4; i++) {
        int f = t + i * 256;
        row_g[i] = f >> 3;       // 0..127
        c4_g[i]  = f & 7;        // float4 column 0..7
    }

    float4 pa[4], pb[4];
    // prologue: load k0=0 tile
#pragma unroll
    for (int i = 0; i < 4; i++) {
        pa[i] = *(const float4*)(A  + (m0 + row_g[i]) * lda + c4_g[i] * 4);
        pb[i] = *(const float4*)(Bm + (n0 + row_g[i]) * ldb + c4_g[i] * 4);
    }

    for (int k0 = 0; k0 < K; k0 += 32) {
        // store prefetched tile to smem (converted to tf32)
#pragma unroll
        for (int i = 0; i < 4; i++) {
            uint4 ua = make_uint4(tf32u(pa[i].x), tf32u(pa[i].y), tf32u(pa[i].z), tf32u(pa[i].w));
            uint4 ub = make_uint4(tf32u(pb[i].x), tf32u(pb[i].y), tf32u(pb[i].z), tf32u(pb[i].w));
            *(uint4*)&As[row_g[i] * PAD + c4_g[i] * 4] = ua;
            *(uint4*)&Bs[row_g[i] * PAD + c4_g[i] * 4] = ub;
        }
        __syncthreads();

        // prefetch next tile
        if (k0 + 32 < K) {
#pragma unroll
            for (int i = 0; i < 4; i++) {
                pa[i] = *(const float4*)(A  + (m0 + row_g[i]) * lda + (k0 + 32) + c4_g[i] * 4);
                pb[i] = *(const float4*)(Bm + (n0 + row_g[i]) * ldb + (k0 + 32) + c4_g[i] * 4);
            }
        }

        // compute 4 k8-steps
#pragma unroll
        for (int kk = 0; kk < 4; kk++) {
            const int kb = kk * 8;
            unsigned af[4][4], bf[4][2];
#pragma unroll
            for (int mi = 0; mi < 4; mi++) {
                int m = wm + mi * 16 + grp;
                af[mi][0] = As[m * PAD + kb + qid];
                af[mi][1] = As[(m + 8) * PAD + kb + qid];
                af[mi][2] = As[m * PAD + kb + qid + 4];
                af[mi][3] = As[(m + 8) * PAD + kb + qid + 4];
            }
#pragma unroll
            for (int ni = 0; ni < 4; ni++) {
                int n = wn + ni * 8 + grp;
                bf[ni][0] = Bs[n * PAD + kb + qid];
                bf[ni][1] = Bs[n * PAD + kb + qid + 4];
            }
#pragma unroll
            for (int mi = 0; mi < 4; mi++)
#pragma unroll
                for (int ni = 0; ni < 4; ni++)
                    mma_tf32(acc[mi][ni][0], acc[mi][ni][1], acc[mi][ni][2], acc[mi][ni][3],
                             af[mi][0], af[mi][1], af[mi][2], af[mi][3],
                             bf[ni][0], bf[ni][1]);
        }
        __syncthreads();
    }

    // epilogue
#pragma unroll
    for (int mi = 0; mi < 4; mi++) {
        long r0 = m0 + wm + mi * 16 + grp;
        long r1 = r0 + 8;
#pragma unroll
        for (int ni = 0; ni < 4; ni++) {
            long col = n0 + wn + ni * 8 + qid * 2;
            float bv0 = 0.f, bv1 = 0.f;
            if (bias) { bv0 = bias[col]; bv1 = bias[col + 1]; }
            float v00 = (acc[mi][ni][0] + bv0) * alpha;
            float v01 = (acc[mi][ni][1] + bv1) * alpha;
            float v10 = (acc[mi][ni][2] + bv0) * alpha;
            float v11 = (acc[mi][ni][3] + bv1) * alpha;
            if (ACT == 1) { v00 = tanhf(v00); v01 = tanhf(v01); v10 = tanhf(v10); v11 = tanhf(v11); }
            *(float2*)(C + r0 * ldc + col) = make_float2(v00, v01);
            *(float2*)(C + r1 * ldc + col) = make_float2(v10, v11);
        }
    }
}

// ---------------------------------------------------------------------------
// NN GEMM (batched, fp32 SIMT): C[m,n] = sum_k A[m,k]*B[k,n]. ctx = attn @ v.
// ---------------------------------------------------------------------------
__global__ __launch_bounds__(256)
void gemm_nn_kernel(const float* __restrict__ A, const float* __restrict__ Bm,
                    float* __restrict__ C,
                    int K, int lda, int ldb, int ldc,
                    long sA, long sB, long sC)
{
    A  += (long)blockIdx.z * sA;
    Bm += (long)blockIdx.z * sB;
    C  += (long)blockIdx.z * sC;

    __shared__ float As[16][132];
    __shared__ float Bs[16][132];

    const int t  = threadIdx.x;
    const int tx = t & 15;
    const int ty = t >> 4;
    const long m0 = (long)blockIdx.y * 128;
    const long n0 = (long)blockIdx.x * 128;

    float acc[8][8];
#pragma unroll
    for (int i = 0; i < 8; i++)
#pragma unroll
        for (int j = 0; j < 8; j++) acc[i][j] = 0.f;

    for (int k0 = 0; k0 < K; k0 += 16) {
#pragma unroll
        for (int i = 0; i < 2; i++) {
            int slot = t + i * 256;
            int row = slot >> 2;
            int kv  = (slot & 3) << 2;
            float4 av = *(const float4*)(A + (m0 + row) * lda + k0 + kv);
            As[kv+0][row] = av.x; As[kv+1][row] = av.y;
            As[kv+2][row] = av.z; As[kv+3][row] = av.w;
            int kk = slot >> 5;
            int nv = (slot & 31) << 2;
            float4 bv = *(const float4*)(Bm + (long)(k0 + kk) * ldb + n0 + nv);
            *(float4*)&Bs[kk][nv] = bv;
        }
        __syncthreads();
#pragma unroll
        for (int k = 0; k < 16; k++) {
            float a[8], b[8];
            *(float4*)(a)     = *(const float4*)&As[k][ty * 8];
            *(float4*)(a + 4) = *(const float4*)&As[k][ty * 8 + 4];
            *(float4*)(b)     = *(const float4*)&Bs[k][tx * 8];
            *(float4*)(b + 4) = *(const float4*)&Bs[k][tx * 8 + 4];
#pragma unroll
            for (int i = 0; i < 8; i++)
#pragma unroll
                for (int j = 0; j < 8; j++)
                    acc[i][j] = fmaf(a[i], b[j], acc[i][j]);
        }
        __syncthreads();
    }

#pragma unroll
    for (int i = 0; i < 8; i++) {
        long row = m0 + ty * 8 + i;
        float* crow = C + row * (long)ldc + n0 + tx * 8;
        *(float4*)(crow)     = make_float4(acc[i][0], acc[i][1], acc[i][2], acc[i][3]);
        *(float4*)(crow + 4) = make_float4(acc[i][4], acc[i][5], acc[i][6], acc[i][7]);
    }
}

// ---------------------------------------------------------------------------
// Softmax over T for attention rows (in-place). mask: [B,T] bytes.
// ---------------------------------------------------------------------------
__global__ __launch_bounds__(256)
void attn_softmax_kernel(float* __restrict__ attn, const unsigned char* __restrict__ mask)
{
    int row = blockIdx.x;
    int b   = row & (B_ - 1);
    float* p = attn + (long)row * T_;
    const unsigned char* mrow = mask + (long)b * T_;
    int t = threadIdx.x;
    __shared__ float red[256];

    float x[4];
    float mx = -1e30f;
#pragma unroll
    for (int i = 0; i < 4; i++) {
        int tt = t + i * 256;
        float v = p[tt];
        if (mrow[tt]) v = -1e9f;
        x[i] = v;
        mx = fmaxf(mx, v);
    }
    red[t] = mx; __syncthreads();
    for (int s = 128; s > 0; s >>= 1) {
        if (t < s) red[t] = fmaxf(red[t], red[t + s]);
        __syncthreads();
    }
    mx = red[0]; __syncthreads();

    float sum = 0.f;
#pragma unroll
    for (int i = 0; i < 4; i++) { x[i] = __expf(x[i] - mx); sum += x[i]; }
    red[t] = sum; __syncthreads();
    for (int s = 128; s > 0; s >>= 1) {
        if (t < s) red[t] += red[t + s];
        __syncthreads();
    }
    float inv = 1.f / red[0];
#pragma unroll
    for (int i = 0; i < 4; i++) p[t + i * 256] = x[i] * inv;
}

// ---------------------------------------------------------------------------
// LayerNorm(outs + x). One block per row, D=512.
// ---------------------------------------------------------------------------
__global__ __launch_bounds__(256)
void ln_kernel(const float* __restrict__ outs, const float* __restrict__ x,
               const float* __restrict__ g, const float* __restrict__ bb,
               float* __restrict__ out)
{
    int row = blockIdx.x;
    int t = threadIdx.x;
    const float* o  = outs + (long)row * D_;
    const float* xr = x    + (long)row * D_;
    __shared__ float red[256];

    float v0 = o[t] + xr[t];
    float v1 = o[t + 256] + xr[t + 256];

    red[t] = v0 + v1; __syncthreads();
    for (int s = 128; s > 0; s >>= 1) { if (t < s) red[t] += red[t + s]; __syncthreads(); }
    float mu = red[0] * (1.f / D_); __syncthreads();

    float d0 = v0 - mu, d1 = v1 - mu;
    red[t] = d0 * d0 + d1 * d1; __syncthreads();
    for (int s = 128; s > 0; s >>= 1) { if (t < s) red[t] += red[t + s]; __syncthreads(); }
    float inv = rsqrtf(red[0] * (1.f / D_) + 1e-5f);

    out[(long)row * D_ + t]       = d0 * inv * g[t]       + bb[t];
    out[(long)row * D_ + t + 256] = d1 * inv * g[t + 256] + bb[t + 256];
}

// ---------------------------------------------------------------------------
// 2-way gate
// ---------------------------------------------------------------------------
__global__ __launch_bounds__(128)
void gates_kernel(const float* __restrict__ tok, const float* __restrict__ Wdiv,
                  const float* __restrict__ bdiv, float* __restrict__ gates)
{
    int row = blockIdx.x;
    int t = threadIdx.x;
    const float* x = tok + (long)row * D_;
    float z0 = 0.f, z1 = 0.f;
    for (int d = t; d < D_; d += 128) {
        float xv = x[d];
        z0 = fmaf(xv, Wdiv[d],      z0);
        z1 = fmaf(xv, Wdiv[D_ + d], z1);
    }
    __shared__ float r0[128], r1[128];
    r0[t] = z0; r1[t] = z1; __syncthreads();
    for (int s = 64; s > 0; s >>= 1) {
        if (t < s) { r0[t] += r0[t + s]; r1[t] += r1[t + s]; }
        __syncthreads();
    }
    if (t == 0) {
        float a = r0[0] + bdiv[0], b = r1[0] + bdiv[1];
        float m = fmaxf(a, b);
        float e0 = __expf(a - m), e1 = __expf(b - m);
        float inv = 1.f / (e0 + e1);
        gates[row * 2 + 0] = e0 * inv;
        gates[row * 2 + 1] = e1 * inv;
    }
}

// ---------------------------------------------------------------------------
// Online softmax stats over V per row; coef = log(gen) - log(sum) - max.
// ---------------------------------------------------------------------------
__global__ __launch_bounds__(256)
void rowstats_kernel(const float* __restrict__ logits,
                     const float* __restrict__ gates, float* __restrict__ coef)
{
    int row = blockIdx.x;
    int t = threadIdx.x;
    const float* z = logits + (long)row * V_;
    float m = -1e30f, s = 0.f;
    for (int j = t; j < V_; j += 256) {
        float v = z[j];
        if (v > m) { s = s * __expf(m - v) + 1.f; m = v; }
        else       { s += __expf(v - m); }
    }
    __shared__ float sm[256], ss[256];
    sm[t] = m; ss[t] = s; __syncthreads();
    for (int k = 128; k > 0; k >>= 1) {
        if (t < k) {
            float m1 = sm[t], s1 = ss[t], m2 = sm[t + k], s2 = ss[t + k];
            float M = fmaxf(m1, m2);
            sm[t] = M;
            ss[t] = s1 * __expf(m1 - M) + s2 * __expf(m2 - M);
        }
        __syncthreads();
    }
    if (t == 0)
        coef[row] = __logf(gates[row * 2 + 0]) - __logf(ss[0]) - sm[0];
}

// ---------------------------------------------------------------------------
// Log-prob base pass: out = coef[row] + z (no MUFU).
// ---------------------------------------------------------------------------
__global__ __launch_bounds__(256)
void lp_kernel(float* __restrict__ out, const float* __restrict__ coef)
{
    long i4 = (long)blockIdx.x * 256 + threadIdx.x;
    int row = (int)(i4 / (V_ / 4));
    float c = __ldg(coef + row);
    float4* p = (float4*)out + i4;
    float4 v = *p;
    v.x += c; v.y += c; v.z += c; v.w += c;
    *p = v;
}

// ---------------------------------------------------------------------------
// Copy-scatter in log space: ll <- log(exp(ll) + copy_val) via CAS.
// ---------------------------------------------------------------------------
__global__ __launch_bounds__(256)
void scatter_kernel(float* __restrict__ out, const float* __restrict__ attn,
                    const float* __restrict__ gates, const int* __restrict__ copy_seq)
{
    int gid = blockIdx.x * 256 + threadIdx.x;
    int row = gid >> 10;
    int t   = gid & 1023;
    int b   = row & (B_ - 1);
    float val = gates[row * 2 + 1] * attn[(long)row * T_ + t];
    int idx = copy_seq[t * B_ + b];
    int* ia = (int*)(out + (long)row * V_ + idx);

    int assumed = *ia;
    int old;
    do {
        old = assumed;
        float cur = __int_as_float(old);
        float nv = __logf(__expf(cur) + val);
        assumed = atomicCAS(ia, old, __float_as_int(nv));
    } while (assumed != old);
}

// ---------------------------------------------------------------------------
// Launch
// ---------------------------------------------------------------------------
extern "C" void kernel_launch(void* const* d_in, const int* in_sizes, int n_in,
                              void* d_out, int out_size)
{
    const float* outs = (const float*)d_in[0];
    const float* gs   = (const float*)d_in[1];
    const unsigned char* mask = (const unsigned char*)d_in[2];
    const int*   cseq = (const int*)d_in[3];
    const float* Wq = (const float*)d_in[4],  *bq = (const float*)d_in[5];
    const float* Wk = (const float*)d_in[6],  *bk = (const float*)d_in[7];
    const float* Wv = (const float*)d_in[8],  *bv = (const float*)d_in[9];
    const float* Wo = (const float*)d_in[10], *bo = (const float*)d_in[11];
    const float* lng = (const float*)d_in[12], *lnb = (const float*)d_in[13];
    const float* Wt = (const float*)d_in[14], *bt = (const float*)d_in[15];
    const float* Wgen = (const float*)d_in[16], *bgen = (const float*)d_in[17];
    const float* Wdiv = (const float*)d_in[18], *bdiv = (const float*)d_in[19];
    float* out = (float*)d_out;

    float* sc = nullptr;
    cudaGetSymbolAddress((void**)&sc, g_scratch);
    float* q    = sc + OQ;   // also reused as x after attention
    float* k    = sc + OK_;
    float* v    = sc + OV;
    float* attn = sc + OA;
    float* ctx  = sc + OC;
    float* ln   = sc + OL;
    float* tok  = sc + OT;
    float* gts  = sc + OG;
    float* coef = sc + OM;

    const float scale = 0.044194173824159216f; // 1/sqrt(512)
    dim3 blk(256);

    // q = (outs @ Wq^T + bq) * scale       [2048 x 512]
    mma_nt_kernel<0><<<dim3(4, 16, 1), blk>>>(outs, Wq, bq, q, D_, D_, D_, D_, 0, 0, 0, scale);
    // k = gs @ Wk^T + bk                   [8192 x 512]
    mma_nt_kernel<0><<<dim3(4, 64, 1), blk>>>(gs, Wk, bk, k, D_, D_, D_, D_, 0, 0, 0, 1.f);
    // v = gs @ Wv^T + bv
    mma_nt_kernel<0><<<dim3(4, 64, 1), blk>>>(gs, Wv, bv, v, D_, D_, D_, D_, 0, 0, 0, 1.f);
    // scores[s,b,t] = q[s,b,:] . k[t,b,:]  (batched over b)
    mma_nt_kernel<0><<<dim3(8, 2, 8), blk>>>(q, k, nullptr, attn,
                                             D_, B_ * D_, B_ * D_, B_ * T_,
                                             D_, D_, T_, 1.f);
    // softmax over t (with mask)
    attn_softmax_kernel<<<SB, 256>>>(attn, mask);
    // ctx[s,b,:] = attn[s,b,:] @ v[:,b,:]
    gemm_nn_kernel<<<dim3(4, 2, 8), blk>>>(attn, v, ctx,
                                           T_, B_ * T_, B_ * D_, B_ * D_,
                                           T_, D_, D_);
    // x = ctx @ Wo^T + bo   -> reuse q buffer
    mma_nt_kernel<0><<<dim3(4, 16, 1), blk>>>(ctx, Wo, bo, q, D_, D_, D_, D_, 0, 0, 0, 1.f);
    // outs_ln = LN(outs + x)
    ln_kernel<<<SB, 256>>>(outs, q, lng, lnb, ln);
    // tok = tanh(outs_ln @ Wt^T + bt)
    mma_nt_kernel<1><<<dim3(4, 16, 1), blk>>>(ln, Wt, bt, tok, D_, D_, D_, TS_, 0, 0, 0, 1.f);
    // gates
    gates_kernel<<<SB, 128>>>(tok, Wdiv, bdiv, gts);
    // logits = tok @ Wgen^T + bgen  -> d_out   [2048 x 32000]
    mma_nt_kernel<0><<<dim3(250, 16, 1), blk>>>(tok, Wgen, bgen, out, D_, TS_, TS_, V_, 0, 0, 0, 1.f);
    // per-row softmax stats -> coef = log(gen) - log(sum) - max
    rowstats_kernel<<<SB, 256>>>(out, gts, coef);
    // base log-probs in place
    lp_kernel<<<(SB * (V_ / 4)) / 256, 256>>>(out, coef);
    // copy scatter (log-space CAS merge)
    scatter_kernel<<<(SB * T_) / 256, 256>>>(out, attn, gts, cseq);
}

// round 4
// speedup vs baseline: 4.5913x; 1.3789x over previous
#include <cuda_runtime.h>
#include <math.h>
#include <stdint.h>

// Problem dims (fixed for this dataset)
constexpr int S_  = 256;
constexpr int B_  = 8;
constexpr int T_  = 1024;
constexpr int D_  = 512;
constexpr int TS_ = 512;
constexpr int V_  = 32000;
constexpr int SB  = S_ * B_;   // 2048
constexpr int TB  = T_ * B_;   // 8192

// ---------------------------------------------------------------------------
// Scratch arena
// ---------------------------------------------------------------------------
constexpr size_t OQ  = 0;                       // q / later x      : SB*D
constexpr size_t OK_ = OQ  + (size_t)SB * D_;   // k                : TB*D
constexpr size_t OV  = OK_ + (size_t)TB * D_;   // v                : TB*D
constexpr size_t OVT = OV  + (size_t)TB * D_;   // v transposed     : TB*D
constexpr size_t OA  = OVT + (size_t)TB * D_;   // attn (scores)    : SB*T
constexpr size_t OC  = OA  + (size_t)SB * T_;   // ctx              : SB*D
constexpr size_t OL  = OC  + (size_t)SB * D_;   // layernorm out    : SB*D
constexpr size_t OT  = OL  + (size_t)SB * D_;   // outs_token       : SB*D
constexpr size_t OG  = OT  + (size_t)SB * D_;   // gates            : SB*2
constexpr size_t OM  = OG  + (size_t)SB * 2;    // per-row coef     : SB
constexpr size_t SCRATCH_FLOATS = OM + SB;

__device__ float g_scratch[SCRATCH_FLOATS];

// ---------------------------------------------------------------------------
// mma helpers
// ---------------------------------------------------------------------------
__device__ __forceinline__ void mma_tf32(float& c0, float& c1, float& c2, float& c3,
                                         unsigned a0, unsigned a1, unsigned a2, unsigned a3,
                                         unsigned b0, unsigned b1)
{
    asm volatile(
        "mma.sync.aligned.m16n8k8.row.col.f32.tf32.tf32.f32 "
        "{%0,%1,%2,%3}, {%4,%5,%6,%7}, {%8,%9}, {%0,%1,%2,%3};"
        : "+f"(c0), "+f"(c1), "+f"(c2), "+f"(c3)
        : "r"(a0), "r"(a1), "r"(a2), "r"(a3), "r"(b0), "r"(b1));
}

__device__ __forceinline__ void cp16(unsigned dst, const void* src) {
    asm volatile("cp.async.cg.shared.global [%0], [%1], 16;\n" :: "r"(dst), "l"(src));
}

// ---------------------------------------------------------------------------
// Tensor-core NT GEMM (tf32, truncated fp32 inputs):
//   C[m,n] = ACT(alpha*(sum_k A[m,k]*B[n,k] + bias[n]))
// BM=BN=128, BK=32, 256 threads (8 warps, warp tile 64x32), cp.async
// double-buffered, XOR-swizzled SMEM (conflict-free), 2 CTAs/SM.
// Dynamic SMEM: 64 KB = 2 stages x (16KB A + 16KB B).
// blockIdx.z batches via sA/sB/sC element strides. All dims tile-divisible.
// ---------------------------------------------------------------------------
template <int ACT>
__global__ __launch_bounds__(256, 2)
void mma_nt_kernel(const float* __restrict__ A, const float* __restrict__ Bm,
                   const float* __restrict__ bias, float* __restrict__ C,
                   int K, int lda, int ldb, int ldc,
                   long sA, long sB, long sC, float alpha)
{
    extern __shared__ unsigned sh[];   // A: [2][4096] at 0; B: [2][4096] at 8192

    A  += (long)blockIdx.z * sA;
    Bm += (long)blockIdx.z * sB;
    C  += (long)blockIdx.z * sC;

    const int t    = threadIdx.x;
    const int lane = t & 31;
    const int warp = t >> 5;
    const int wm   = (warp >> 2) * 64;      // 0 or 64
    const int wn   = (warp & 3) * 32;       // 0,32,64,96
    const int grp  = lane >> 2;             // 0..7
    const int qid  = lane & 3;              // 0..3

    const long m0 = (long)blockIdx.y * 128;
    const long n0 = (long)blockIdx.x * 128;

    float acc[4][4][4];
#pragma unroll
    for (int mi = 0; mi < 4; mi++)
#pragma unroll
        for (int ni = 0; ni < 4; ni++)
#pragma unroll
            for (int c = 0; c < 4; c++) acc[mi][ni][c] = 0.f;

    // global<->smem mapping: 1024 float4 per operand tile, 4 per thread
    const float* aptr[4];
    const float* bptr[4];
    unsigned soff[4];                        // swizzled byte offset in stage
#pragma unroll
    for (int i = 0; i < 4; i++) {
        int f   = t + i * 256;
        int row = f >> 3;                    // 0..127
        int c4  = f & 7;                     // float4 col
        aptr[i] = A  + (m0 + row) * lda + c4 * 4;
        bptr[i] = Bm + (n0 + row) * ldb + c4 * 4;
        soff[i] = (unsigned)(row * 32 + ((c4 ^ (row & 7)) << 2)) * 4u;
    }
    const unsigned sbase = (unsigned)__cvta_generic_to_shared(sh);

    auto issue = [&](int stage, int koff) {
        unsigned ab = sbase + (unsigned)stage * 16384u;
        unsigned bb = sbase + 32768u + (unsigned)stage * 16384u;
#pragma unroll
        for (int i = 0; i < 4; i++) {
            cp16(ab + soff[i], aptr[i] + koff);
            cp16(bb + soff[i], bptr[i] + koff);
        }
        asm volatile("cp.async.commit_group;\n" ::: "memory");
    };

    issue(0, 0);
    const int nIter = K >> 5;
    for (int it = 0; it < nIter; ++it) {
        asm volatile("cp.async.wait_group 0;\n" ::: "memory");
        __syncthreads();
        if (it + 1 < nIter) issue((it + 1) & 1, (it + 1) * 32);

        const unsigned* Asb = sh + (it & 1) * 4096;
        const unsigned* Bsb = sh + 8192 + (it & 1) * 4096;
#pragma unroll
        for (int kk = 0; kk < 4; kk++) {
            unsigned af[4][4], bf[4][2];
#pragma unroll
            for (int mi = 0; mi < 4; mi++) {
                int m  = wm + mi * 16 + grp;
                int m8 = m + 8;
                af[mi][0] = Asb[m  * 32 + ((( kk * 2    ) ^ (m  & 7)) << 2) + qid];
                af[mi][1] = Asb[m8 * 32 + ((( kk * 2    ) ^ (m8 & 7)) << 2) + qid];
                af[mi][2] = Asb[m  * 32 + ((( kk * 2 + 1) ^ (m  & 7)) << 2) + qid];
                af[mi][3] = Asb[m8 * 32 + ((( kk * 2 + 1) ^ (m8 & 7)) << 2) + qid];
            }
#pragma unroll
            for (int ni = 0; ni < 4; ni++) {
                int n = wn + ni * 8 + grp;
                bf[ni][0] = Bsb[n * 32 + ((( kk * 2    ) ^ (n & 7)) << 2) + qid];
                bf[ni][1] = Bsb[n * 32 + ((( kk * 2 + 1) ^ (n & 7)) << 2) + qid];
            }
#pragma unroll
            for (int mi = 0; mi < 4; mi++)
#pragma unroll
                for (int ni = 0; ni < 4; ni++)
                    mma_tf32(acc[mi][ni][0], acc[mi][ni][1], acc[mi][ni][2], acc[mi][ni][3],
                             af[mi][0], af[mi][1], af[mi][2], af[mi][3],
                             bf[ni][0], bf[ni][1]);
        }
        __syncthreads();
    }

    // epilogue
#pragma unroll
    for (int mi = 0; mi < 4; mi++) {
        long r0 = m0 + wm + mi * 16 + grp;
        long r1 = r0 + 8;
#pragma unroll
        for (int ni = 0; ni < 4; ni++) {
            long col = n0 + wn + ni * 8 + qid * 2;
            float bv0 = 0.f, bv1 = 0.f;
            if (bias) { bv0 = bias[col]; bv1 = bias[col + 1]; }
            float v00 = (acc[mi][ni][0] + bv0) * alpha;
            float v01 = (acc[mi][ni][1] + bv1) * alpha;
            float v10 = (acc[mi][ni][2] + bv0) * alpha;
            float v11 = (acc[mi][ni][3] + bv1) * alpha;
            if (ACT == 1) { v00 = tanhf(v00); v01 = tanhf(v01); v10 = tanhf(v10); v11 = tanhf(v11); }
            *(float2*)(C + r0 * ldc + col) = make_float2(v00, v01);
            *(float2*)(C + r1 * ldc + col) = make_float2(v10, v11);
        }
    }
}

// ---------------------------------------------------------------------------
// v transpose: vt[b][d][t] = v[(t*B+b)*D + d].  32x32 tiles.
// ---------------------------------------------------------------------------
__global__ __launch_bounds__(256)
void vt_kernel(const float* __restrict__ v, float* __restrict__ vt)
{
    __shared__ float tile[32][33];
    int b  = blockIdx.z;
    int t0 = blockIdx.x * 32;
    int d0 = blockIdx.y * 32;
    int x  = threadIdx.x & 31;
    int y  = threadIdx.x >> 5;      // 0..7
#pragma unroll
    for (int j = 0; j < 32; j += 8)
        tile[y + j][x] = v[((long)(t0 + y + j) * B_ + b) * D_ + d0 + x];
    __syncthreads();
#pragma unroll
    for (int j = 0; j < 32; j += 8)
        vt[(long)b * D_ * T_ + (long)(d0 + y + j) * T_ + t0 + x] = tile[x][y + j];
}

// ---------------------------------------------------------------------------
// Softmax over T for attention rows (in-place). mask: [B,T] bytes.
// ---------------------------------------------------------------------------
__global__ __launch_bounds__(256)
void attn_softmax_kernel(float* __restrict__ attn, const unsigned char* __restrict__ mask)
{
    int row = blockIdx.x;
    int b   = row & (B_ - 1);
    float* p = attn + (long)row * T_;
    const unsigned char* mrow = mask + (long)b * T_;
    int t = threadIdx.x;
    __shared__ float red[256];

    float x[4];
    float mx = -1e30f;
#pragma unroll
    for (int i = 0; i < 4; i++) {
        int tt = t + i * 256;
        float v = p[tt];
        if (mrow[tt]) v = -1e9f;
        x[i] = v;
        mx = fmaxf(mx, v);
    }
    red[t] = mx; __syncthreads();
    for (int s = 128; s > 0; s >>= 1) {
        if (t < s) red[t] = fmaxf(red[t], red[t + s]);
        __syncthreads();
    }
    mx = red[0]; __syncthreads();

    float sum = 0.f;
#pragma unroll
    for (int i = 0; i < 4; i++) { x[i] = __expf(x[i] - mx); sum += x[i]; }
    red[t] = sum; __syncthreads();
    for (int s = 128; s > 0; s >>= 1) {
        if (t < s) red[t] += red[t + s];
        __syncthreads();
    }
    float inv = 1.f / red[0];
#pragma unroll
    for (int i = 0; i < 4; i++) p[t + i * 256] = x[i] * inv;
}

// ---------------------------------------------------------------------------
// LayerNorm(outs + x). One block per row, D=512.
// ---------------------------------------------------------------------------
__global__ __launch_bounds__(256)
void ln_kernel(const float* __restrict__ outs, const float* __restrict__ x,
               const float* __restrict__ g, const float* __restrict__ bb,
               float* __restrict__ out)
{
    int row = blockIdx.x;
    int t = threadIdx.x;
    const float* o  = outs + (long)row * D_;
    const float* xr = x    + (long)row * D_;
    __shared__ float red[256];

    float v0 = o[t] + xr[t];
    float v1 = o[t + 256] + xr[t + 256];

    red[t] = v0 + v1; __syncthreads();
    for (int s = 128; s > 0; s >>= 1) { if (t < s) red[t] += red[t + s]; __syncthreads(); }
    float mu = red[0] * (1.f / D_); __syncthreads();

    float d0 = v0 - mu, d1 = v1 - mu;
    red[t] = d0 * d0 + d1 * d1; __syncthreads();
    for (int s = 128; s > 0; s >>= 1) { if (t < s) red[t] += red[t + s]; __syncthreads(); }
    float inv = rsqrtf(red[0] * (1.f / D_) + 1e-5f);

    out[(long)row * D_ + t]       = d0 * inv * g[t]       + bb[t];
    out[(long)row * D_ + t + 256] = d1 * inv * g[t + 256] + bb[t + 256];
}

// ---------------------------------------------------------------------------
// 2-way gate
// ---------------------------------------------------------------------------
__global__ __launch_bounds__(128)
void gates_kernel(const float* __restrict__ tok, const float* __restrict__ Wdiv,
                  const float* __restrict__ bdiv, float* __restrict__ gates)
{
    int row = blockIdx.x;
    int t = threadIdx.x;
    const float* x = tok + (long)row * D_;
    float z0 = 0.f, z1 = 0.f;
    for (int d = t; d < D_; d += 128) {
        float xv = x[d];
        z0 = fmaf(xv, Wdiv[d],      z0);
        z1 = fmaf(xv, Wdiv[D_ + d], z1);
    }
    __shared__ float r0[128], r1[128];
    r0[t] = z0; r1[t] = z1; __syncthreads();
    for (int s = 64; s > 0; s >>= 1) {
        if (t < s) { r0[t] += r0[t + s]; r1[t] += r1[t + s]; }
        __syncthreads();
    }
    if (t == 0) {
        float a = r0[0] + bdiv[0], b = r1[0] + bdiv[1];
        float m = fmaxf(a, b);
        float e0 = __expf(a - m), e1 = __expf(b - m);
        float inv = 1.f / (e0 + e1);
        gates[row * 2 + 0] = e0 * inv;
        gates[row * 2 + 1] = e1 * inv;
    }
}

// ---------------------------------------------------------------------------
// Online softmax stats over V per row; coef = log(gen) - log(sum) - max.
// float4 loads.
// ---------------------------------------------------------------------------
__global__ __launch_bounds__(256)
void rowstats_kernel(const float* __restrict__ logits,
                     const float* __restrict__ gates, float* __restrict__ coef)
{
    int row = blockIdx.x;
    int t = threadIdx.x;
    const float4* z4 = (const float4*)(logits + (long)row * V_);
    float m = -1e30f, s = 0.f;
    for (int j = t; j < V_ / 4; j += 256) {
        float4 v4 = z4[j];
        float vv[4] = {v4.x, v4.y, v4.z, v4.w};
#pragma unroll
        for (int u = 0; u < 4; u++) {
            float v = vv[u];
            if (v > m) { s = s * __expf(m - v) + 1.f; m = v; }
            else       { s += __expf(v - m); }
        }
    }
    __shared__ float sm[256], ss[256];
    sm[t] = m; ss[t] = s; __syncthreads();
    for (int k = 128; k > 0; k >>= 1) {
        if (t < k) {
            float m1 = sm[t], s1 = ss[t], m2 = sm[t + k], s2 = ss[t + k];
            float M = fmaxf(m1, m2);
            sm[t] = M;
            ss[t] = s1 * __expf(m1 - M) + s2 * __expf(m2 - M);
        }
        __syncthreads();
    }
    if (t == 0)
        coef[row] = __logf(gates[row * 2 + 0]) - __logf(ss[0]) - sm[0];
}

// ---------------------------------------------------------------------------
// Log-prob base pass: out = coef[row] + z (no MUFU).
// ---------------------------------------------------------------------------
__global__ __launch_bounds__(256)
void lp_kernel(float* __restrict__ out, const float* __restrict__ coef)
{
    long i4 = (long)blockIdx.x * 256 + threadIdx.x;
    int row = (int)(i4 / (V_ / 4));
    float c = __ldg(coef + row);
    float4* p = (float4*)out + i4;
    float4 v = *p;
    v.x += c; v.y += c; v.z += c; v.w += c;
    *p = v;
}

// ---------------------------------------------------------------------------
// Copy-scatter in log space: ll <- log(exp(ll) + copy_val) via CAS.
// ---------------------------------------------------------------------------
__global__ __launch_bounds__(256)
void scatter_kernel(float* __restrict__ out, const float* __restrict__ attn,
                    const float* __restrict__ gates, const int* __restrict__ copy_seq)
{
    int gid = blockIdx.x * 256 + threadIdx.x;
    int row = gid >> 10;
    int t   = gid & 1023;
    int b   = row & (B_ - 1);
    float val = gates[row * 2 + 1] * attn[(long)row * T_ + t];
    int idx = copy_seq[t * B_ + b];
    int* ia = (int*)(out + (long)row * V_ + idx);

    int assumed = *ia;
    int old;
    do {
        old = assumed;
        float cur = __int_as_float(old);
        float nv = __logf(__expf(cur) + val);
        assumed = atomicCAS(ia, old, __float_as_int(nv));
    } while (assumed != old);
}

// ---------------------------------------------------------------------------
// Launch
// ---------------------------------------------------------------------------
extern "C" void kernel_launch(void* const* d_in, const int* in_sizes, int n_in,
                              void* d_out, int out_size)
{
    const float* outs = (const float*)d_in[0];
    const float* gs   = (const float*)d_in[1];
    const unsigned char* mask = (const unsigned char*)d_in[2];
    const int*   cseq = (const int*)d_in[3];
    const float* Wq = (const float*)d_in[4],  *bq = (const float*)d_in[5];
    const float* Wk = (const float*)d_in[6],  *bk = (const float*)d_in[7];
    const float* Wv = (const float*)d_in[8],  *bv = (const float*)d_in[9];
    const float* Wo = (const float*)d_in[10], *bo = (const float*)d_in[11];
    const float* lng = (const float*)d_in[12], *lnb = (const float*)d_in[13];
    const float* Wt = (const float*)d_in[14], *bt = (const float*)d_in[15];
    const float* Wgen = (const float*)d_in[16], *bgen = (const float*)d_in[17];
    const float* Wdiv = (const float*)d_in[18], *bdiv = (const float*)d_in[19];
    float* out = (float*)d_out;

    float* sc = nullptr;
    cudaGetSymbolAddress((void**)&sc, g_scratch);
    float* q    = sc + OQ;   // also reused as x after attention
    float* k    = sc + OK_;
    float* v    = sc + OV;
    float* vt   = sc + OVT;
    float* attn = sc + OA;
    float* ctx  = sc + OC;
    float* ln   = sc + OL;
    float* tok  = sc + OT;
    float* gts  = sc + OG;
    float* coef = sc + OM;

    const float scale = 0.044194173824159216f; // 1/sqrt(512)
    constexpr int SMEM = 65536;
    cudaFuncSetAttribute(mma_nt_kernel<0>, cudaFuncAttributeMaxDynamicSharedMemorySize, SMEM);
    cudaFuncSetAttribute(mma_nt_kernel<1>, cudaFuncAttributeMaxDynamicSharedMemorySize, SMEM);
    dim3 blk(256);

    // q = (outs @ Wq^T + bq) * scale       [2048 x 512]
    mma_nt_kernel<0><<<dim3(4, 16, 1), blk, SMEM>>>(outs, Wq, bq, q, D_, D_, D_, D_, 0, 0, 0, scale);
    // k = gs @ Wk^T + bk                   [8192 x 512]
    mma_nt_kernel<0><<<dim3(4, 64, 1), blk, SMEM>>>(gs, Wk, bk, k, D_, D_, D_, D_, 0, 0, 0, 1.f);
    // v = gs @ Wv^T + bv
    mma_nt_kernel<0><<<dim3(4, 64, 1), blk, SMEM>>>(gs, Wv, bv, v, D_, D_, D_, D_, 0, 0, 0, 1.f);
    // v transpose for ctx GEMM
    vt_kernel<<<dim3(32, 16, 8), blk>>>(v, vt);
    // scores[s,b,t] = q[s,b,:] . k[t,b,:]  (batched over b)
    mma_nt_kernel<0><<<dim3(8, 2, 8), blk, SMEM>>>(q, k, nullptr, attn,
                                                   D_, B_ * D_, B_ * D_, B_ * T_,
                                                   D_, D_, T_, 1.f);
    // softmax over t (with mask)
    attn_softmax_kernel<<<SB, 256>>>(attn, mask);
    // ctx[s,b,:] = attn[s,b,:] @ v[:,b,:]   (NT vs v_T, batched over b)
    mma_nt_kernel<0><<<dim3(4, 2, 8), blk, SMEM>>>(attn, vt, nullptr, ctx,
                                                   T_, B_ * T_, T_, B_ * D_,
                                                   T_, (long)D_ * T_, D_, 1.f);
    // x = ctx @ Wo^T + bo   -> reuse q buffer
    mma_nt_kernel<0><<<dim3(4, 16, 1), blk, SMEM>>>(ctx, Wo, bo, q, D_, D_, D_, D_, 0, 0, 0, 1.f);
    // outs_ln = LN(outs + x)
    ln_kernel<<<SB, 256>>>(outs, q, lng, lnb, ln);
    // tok = tanh(outs_ln @ Wt^T + bt)
    mma_nt_kernel<1><<<dim3(4, 16, 1), blk, SMEM>>>(ln, Wt, bt, tok, D_, D_, D_, TS_, 0, 0, 0, 1.f);
    // gates
    gates_kernel<<<SB, 128>>>(tok, Wdiv, bdiv, gts);
    // logits = tok @ Wgen^T + bgen  -> d_out   [2048 x 32000]
    mma_nt_kernel<0><<<dim3(250, 16, 1), blk, SMEM>>>(tok, Wgen, bgen, out, D_, TS_, TS_, V_, 0, 0, 0, 1.f);
    // per-row softmax stats -> coef = log(gen) - log(sum) - max
    rowstats_kernel<<<SB, 256>>>(out, gts, coef);
    // base log-probs in place
    lp_kernel<<<(SB * (V_ / 4)) / 256, 256>>>(out, coef);
    // copy scatter (log-space CAS merge)
    scatter_kernel<<<(SB * T_) / 256, 256>>>(out, attn, gts, cseq);
}

// round 5
// speedup vs baseline: 6.2992x; 1.3720x over previous
#include <cuda_runtime.h>
#include <cuda_bf16.h>
#include <math.h>
#include <stdint.h>

// Problem dims (fixed for this dataset)
constexpr int S_  = 256;
constexpr int B_  = 8;
constexpr int T_  = 1024;
constexpr int D_  = 512;
constexpr int TS_ = 512;
constexpr int V_  = 32000;
constexpr int SB  = S_ * B_;   // 2048
constexpr int TB  = T_ * B_;   // 8192

// ---------------------------------------------------------------------------
// Scratch arena
// ---------------------------------------------------------------------------
constexpr size_t OQ  = 0;                        // q / later x      : SB*D
constexpr size_t OK_ = OQ  + (size_t)SB * D_;    // k                : TB*D
constexpr size_t OV  = OK_ + (size_t)TB * D_;    // v                : TB*D
constexpr size_t OVT = OV  + (size_t)TB * D_;    // v transposed     : TB*D
constexpr size_t OA  = OVT + (size_t)TB * D_;    // attn (scores)    : SB*T
constexpr size_t OC  = OA  + (size_t)SB * T_;    // ctx              : SB*D
constexpr size_t OL  = OC  + (size_t)SB * D_;    // layernorm out    : SB*D
constexpr size_t OT  = OL  + (size_t)SB * D_;    // outs_token (f32) : SB*D
constexpr size_t OG  = OT  + (size_t)SB * D_;    // gates            : SB*2
constexpr size_t OM  = OG  + (size_t)SB * 2;     // per-row coef     : SB
constexpr size_t ORS = OM  + SB;                 // rowsum exp       : SB
constexpr size_t OWB = ORS + SB;                 // Wgen bf16        : V*TS/2 floats
constexpr size_t OTB = OWB + (size_t)V_ * TS_ / 2;  // tok bf16      : SB*TS/2
constexpr size_t SCRATCH_FLOATS = OTB + (size_t)SB * TS_ / 2;

__device__ float g_scratch[SCRATCH_FLOATS];

// ---------------------------------------------------------------------------
// math helpers
// ---------------------------------------------------------------------------
// fast exp on FMA pipe: exp(x) = 2^(x*log2e), clamped; |rel err| ~1e-7
__device__ __forceinline__ float fexp(float x) {
    float t = fmaxf(fminf(x * 1.4426950408889634f, 126.f), -126.f);
    float mg = t + 12582912.f;                    // round-to-nearest int
    int   n  = __float_as_int(mg) - 0x4B400000;   // integer part
    float f  = t - (mg - 12582912.f);             // frac in [-0.5,0.5]
    float p  = 1.54035304e-4f;
    p = fmaf(p, f, 1.33335581e-3f);
    p = fmaf(p, f, 9.61812911e-3f);
    p = fmaf(p, f, 5.55041087e-2f);
    p = fmaf(p, f, 2.40226507e-1f);
    p = fmaf(p, f, 6.93147182e-1f);
    p = fmaf(p, f, 1.0f);
    return __int_as_float(__float_as_int(p) + (n << 23));
}

__device__ __forceinline__ void mma_tf32(float& c0, float& c1, float& c2, float& c3,
                                         unsigned a0, unsigned a1, unsigned a2, unsigned a3,
                                         unsigned b0, unsigned b1)
{
    asm volatile(
        "mma.sync.aligned.m16n8k8.row.col.f32.tf32.tf32.f32 "
        "{%0,%1,%2,%3}, {%4,%5,%6,%7}, {%8,%9}, {%0,%1,%2,%3};"
        : "+f"(c0), "+f"(c1), "+f"(c2), "+f"(c3)
        : "r"(a0), "r"(a1), "r"(a2), "r"(a3), "r"(b0), "r"(b1));
}

__device__ __forceinline__ void mma_bf16(float& c0, float& c1, float& c2, float& c3,
                                         unsigned a0, unsigned a1, unsigned a2, unsigned a3,
                                         unsigned b0, unsigned b1)
{
    asm volatile(
        "mma.sync.aligned.m16n8k16.row.col.f32.bf16.bf16.f32 "
        "{%0,%1,%2,%3}, {%4,%5,%6,%7}, {%8,%9}, {%0,%1,%2,%3};"
        : "+f"(c0), "+f"(c1), "+f"(c2), "+f"(c3)
        : "r"(a0), "r"(a1), "r"(a2), "r"(a3), "r"(b0), "r"(b1));
}

__device__ __forceinline__ void cp16(unsigned dst, const void* src) {
    asm volatile("cp.async.cg.shared.global [%0], [%1], 16;\n" :: "r"(dst), "l"(src));
}

// ---------------------------------------------------------------------------
// Tensor-core NT GEMM (tf32, truncated fp32 inputs):
//   C[m,n] = ACT(alpha*(sum_k A[m,k]*B[n,k] + bias[n]))
// BM=BN=128, BK=32, 256 threads (8 warps, 64x32 warp tiles), cp.async
// double-buffered, XOR-swizzled SMEM, 2 CTAs/SM. Dyn SMEM 64KB.
// ---------------------------------------------------------------------------
template <int ACT>
__global__ __launch_bounds__(256, 2)
void mma_nt_kernel(const float* __restrict__ A, const float* __restrict__ Bm,
                   const float* __restrict__ bias, float* __restrict__ C,
                   int K, int lda, int ldb, int ldc,
                   long sA, long sB, long sC, float alpha)
{
    extern __shared__ unsigned sh[];

    A  += (long)blockIdx.z * sA;
    Bm += (long)blockIdx.z * sB;
    C  += (long)blockIdx.z * sC;

    const int t    = threadIdx.x;
    const int lane = t & 31;
    const int warp = t >> 5;
    const int wm   = (warp >> 2) * 64;
    const int wn   = (warp & 3) * 32;
    const int grp  = lane >> 2;
    const int qid  = lane & 3;

    const long m0 = (long)blockIdx.y * 128;
    const long n0 = (long)blockIdx.x * 128;

    float acc[4][4][4];
#pragma unroll
    for (int mi = 0; mi < 4; mi++)
#pragma unroll
        for (int ni = 0; ni < 4; ni++)
#pragma unroll
            for (int c = 0; c < 4; c++) acc[mi][ni][c] = 0.f;

    const float* aptr[4];
    const float* bptr[4];
    unsigned soff[4];
#pragma unroll
    for (int i = 0; i < 4; i++) {
        int f   = t + i * 256;
        int row = f >> 3;
        int c4  = f & 7;
        aptr[i] = A  + (m0 + row) * lda + c4 * 4;
        bptr[i] = Bm + (n0 + row) * ldb + c4 * 4;
        soff[i] = (unsigned)(row * 32 + ((c4 ^ (row & 7)) << 2)) * 4u;
    }
    const unsigned sbase = (unsigned)__cvta_generic_to_shared(sh);

    auto issue = [&](int stage, int koff) {
        unsigned ab = sbase + (unsigned)stage * 16384u;
        unsigned bb = sbase + 32768u + (unsigned)stage * 16384u;
#pragma unroll
        for (int i = 0; i < 4; i++) {
            cp16(ab + soff[i], aptr[i] + koff);
            cp16(bb + soff[i], bptr[i] + koff);
        }
        asm volatile("cp.async.commit_group;\n" ::: "memory");
    };

    issue(0, 0);
    const int nIter = K >> 5;
    for (int it = 0; it < nIter; ++it) {
        asm volatile("cp.async.wait_group 0;\n" ::: "memory");
        __syncthreads();
        if (it + 1 < nIter) issue((it + 1) & 1, (it + 1) * 32);

        const unsigned* Asb = sh + (it & 1) * 4096;
        const unsigned* Bsb = sh + 8192 + (it & 1) * 4096;
#pragma unroll
        for (int kk = 0; kk < 4; kk++) {
            unsigned af[4][4], bf[4][2];
#pragma unroll
            for (int mi = 0; mi < 4; mi++) {
                int m  = wm + mi * 16 + grp;
                int m8 = m + 8;
                af[mi][0] = Asb[m  * 32 + ((( kk * 2    ) ^ (m  & 7)) << 2) + qid];
                af[mi][1] = Asb[m8 * 32 + ((( kk * 2    ) ^ (m8 & 7)) << 2) + qid];
                af[mi][2] = Asb[m  * 32 + ((( kk * 2 + 1) ^ (m  & 7)) << 2) + qid];
                af[mi][3] = Asb[m8 * 32 + ((( kk * 2 + 1) ^ (m8 & 7)) << 2) + qid];
            }
#pragma unroll
            for (int ni = 0; ni < 4; ni++) {
                int n = wn + ni * 8 + grp;
                bf[ni][0] = Bsb[n * 32 + ((( kk * 2    ) ^ (n & 7)) << 2) + qid];
                bf[ni][1] = Bsb[n * 32 + ((( kk * 2 + 1) ^ (n & 7)) << 2) + qid];
            }
#pragma unroll
            for (int mi = 0; mi < 4; mi++)
#pragma unroll
                for (int ni = 0; ni < 4; ni++)
                    mma_tf32(acc[mi][ni][0], acc[mi][ni][1], acc[mi][ni][2], acc[mi][ni][3],
                             af[mi][0], af[mi][1], af[mi][2], af[mi][3],
                             bf[ni][0], bf[ni][1]);
        }
        __syncthreads();
    }

#pragma unroll
    for (int mi = 0; mi < 4; mi++) {
        long r0 = m0 + wm + mi * 16 + grp;
        long r1 = r0 + 8;
#pragma unroll
        for (int ni = 0; ni < 4; ni++) {
            long col = n0 + wn + ni * 8 + qid * 2;
            float bv0 = 0.f, bv1 = 0.f;
            if (bias) { bv0 = bias[col]; bv1 = bias[col + 1]; }
            float v00 = (acc[mi][ni][0] + bv0) * alpha;
            float v01 = (acc[mi][ni][1] + bv1) * alpha;
            float v10 = (acc[mi][ni][2] + bv0) * alpha;
            float v11 = (acc[mi][ni][3] + bv1) * alpha;
            if (ACT == 1) { v00 = tanhf(v00); v01 = tanhf(v01); v10 = tanhf(v10); v11 = tanhf(v11); }
            *(float2*)(C + r0 * ldc + col) = make_float2(v00, v01);
            *(float2*)(C + r1 * ldc + col) = make_float2(v10, v11);
        }
    }
}

// ---------------------------------------------------------------------------
// Tensor-core NT GEMM (bf16, m16n8k16) with fused exp-rowsum epilogue.
//   C[m,n] = sum_k A[m,k]*B[n,k] + bias[n];  rowsum[m] += sum_n exp(C[m,n])
// BM=BN=128, BK=64. SMEM: 2 stages x (16KB A + 16KB B) = 64KB. 2 CTAs/SM.
// ---------------------------------------------------------------------------
__global__ __launch_bounds__(256, 2)
void mma_bf16_nt_kernel(const __nv_bfloat16* __restrict__ A,
                        const __nv_bfloat16* __restrict__ Bm,
                        const float* __restrict__ bias, float* __restrict__ C,
                        float* __restrict__ rowsum,
                        int K, int lda, int ldb, int ldc)
{
    extern __shared__ unsigned sh[];
    char* shc = (char*)sh;

    const int t    = threadIdx.x;
    const int lane = t & 31;
    const int warp = t >> 5;
    const int wm   = (warp >> 2) * 64;
    const int wn   = (warp & 3) * 32;
    const int grp  = lane >> 2;
    const int qid  = lane & 3;

    const long m0 = (long)blockIdx.y * 128;
    const long n0 = (long)blockIdx.x * 128;

    float acc[4][4][4];
#pragma unroll
    for (int mi = 0; mi < 4; mi++)
#pragma unroll
        for (int ni = 0; ni < 4; ni++)
#pragma unroll
            for (int c = 0; c < 4; c++) acc[mi][ni][c] = 0.f;

    // tile = 128 rows x 64 bf16 (128B) per operand: 1024 x 16B chunks, 4/thread
    const __nv_bfloat16* aptr[4];
    const __nv_bfloat16* bptr[4];
    unsigned soff[4];
#pragma unroll
    for (int i = 0; i < 4; i++) {
        int f   = t + i * 256;
        int row = f >> 3;       // 0..127
        int c8  = f & 7;        // 16B chunk (8 bf16)
        aptr[i] = A  + (m0 + row) * lda + c8 * 8;
        bptr[i] = Bm + (n0 + row) * ldb + c8 * 8;
        soff[i] = (unsigned)(row * 128 + ((c8 ^ (row & 7)) << 4));
    }
    const unsigned sbase = (unsigned)__cvta_generic_to_shared(sh);

    auto issue = [&](int stage, int koff) {
        unsigned ab = sbase + (unsigned)stage * 16384u;
        unsigned bb = sbase + 32768u + (unsigned)stage * 16384u;
#pragma unroll
        for (int i = 0; i < 4; i++) {
            cp16(ab + soff[i], aptr[i] + koff);
            cp16(bb + soff[i], bptr[i] + koff);
        }
        asm volatile("cp.async.commit_group;\n" ::: "memory");
    };

    issue(0, 0);
    const int nIter = K >> 6;                     // BK = 64
    for (int it = 0; it < nIter; ++it) {
        asm volatile("cp.async.wait_group 0;\n" ::: "memory");
        __syncthreads();
        if (it + 1 < nIter) issue((it + 1) & 1, (it + 1) * 64);

        const char* Asb = shc + (it & 1) * 16384;
        const char* Bsb = shc + 32768 + (it & 1) * 16384;
#pragma unroll
        for (int kk = 0; kk < 4; kk++) {          // 16 k per step
            unsigned af[4][4], bf[4][2];
#pragma unroll
            for (int mi = 0; mi < 4; mi++) {
                int m  = wm + mi * 16 + grp;
                int m8 = m + 8;
                af[mi][0] = *(const unsigned*)(Asb + m  * 128 + (((kk*2  ) ^ (m  & 7)) << 4) + qid * 4);
                af[mi][1] = *(const unsigned*)(Asb + m8 * 128 + (((kk*2  ) ^ (m8 & 7)) << 4) + qid * 4);
                af[mi][2] = *(const unsigned*)(Asb + m  * 128 + (((kk*2+1) ^ (m  & 7)) << 4) + qid * 4);
                af[mi][3] = *(const unsigned*)(Asb + m8 * 128 + (((kk*2+1) ^ (m8 & 7)) << 4) + qid * 4);
            }
#pragma unroll
            for (int ni = 0; ni < 4; ni++) {
                int n = wn + ni * 8 + grp;
                bf[ni][0] = *(const unsigned*)(Bsb + n * 128 + (((kk*2  ) ^ (n & 7)) << 4) + qid * 4);
                bf[ni][1] = *(const unsigned*)(Bsb + n * 128 + (((kk*2+1) ^ (n & 7)) << 4) + qid * 4);
            }
#pragma unroll
            for (int mi = 0; mi < 4; mi++)
#pragma unroll
                for (int ni = 0; ni < 4; ni++)
                    mma_bf16(acc[mi][ni][0], acc[mi][ni][1], acc[mi][ni][2], acc[mi][ni][3],
                             af[mi][0], af[mi][1], af[mi][2], af[mi][3],
                             bf[ni][0], bf[ni][1]);
        }
        __syncthreads();
    }

    // epilogue: write logits + accumulate per-row sum of exp
#pragma unroll
    for (int mi = 0; mi < 4; mi++) {
        long r0 = m0 + wm + mi * 16 + grp;
        long r1 = r0 + 8;
        float e0 = 0.f, e1 = 0.f;
#pragma unroll
        for (int ni = 0; ni < 4; ni++) {
            long col = n0 + wn + ni * 8 + qid * 2;
            float bv0 = bias[col], bv1 = bias[col + 1];
            float v00 = acc[mi][ni][0] + bv0;
            float v01 = acc[mi][ni][1] + bv1;
            float v10 = acc[mi][ni][2] + bv0;
            float v11 = acc[mi][ni][3] + bv1;
            *(float2*)(C + r0 * ldc + col) = make_float2(v00, v01);
            *(float2*)(C + r1 * ldc + col) = make_float2(v10, v11);
            e0 += fexp(v00) + fexp(v01);
            e1 += fexp(v10) + fexp(v11);
        }
        e0 += __shfl_xor_sync(0xFFFFFFFFu, e0, 1);
        e0 += __shfl_xor_sync(0xFFFFFFFFu, e0, 2);
        e1 += __shfl_xor_sync(0xFFFFFFFFu, e1, 1);
        e1 += __shfl_xor_sync(0xFFFFFFFFu, e1, 2);
        if (qid == 0) {
            atomicAdd(rowsum + r0, e0);
            atomicAdd(rowsum + r1, e1);
        }
    }
}

// ---------------------------------------------------------------------------
// fp32 -> bf16 convert (float4 granularity)
// ---------------------------------------------------------------------------
__global__ __launch_bounds__(256)
void f2b_kernel(const float4* __restrict__ in, __nv_bfloat162* __restrict__ out, int n4)
{
    int i = blockIdx.x * 256 + threadIdx.x;
    if (i >= n4) return;
    float4 v = in[i];
    out[i * 2]     = __floats2bfloat162_rn(v.x, v.y);
    out[i * 2 + 1] = __floats2bfloat162_rn(v.z, v.w);
}

// ---------------------------------------------------------------------------
// zero rowsum
// ---------------------------------------------------------------------------
__global__ void zero_kernel(float* __restrict__ p)
{
    p[blockIdx.x * 256 + threadIdx.x] = 0.f;
}

// coef[row] = log(gen_gate) - log(rowsum)
__global__ void coef_kernel(const float* __restrict__ rowsum,
                            const float* __restrict__ gates, float* __restrict__ coef)
{
    int r = blockIdx.x * 256 + threadIdx.x;
    coef[r] = __logf(gates[r * 2 + 0]) - __logf(rowsum[r]);
}

// ---------------------------------------------------------------------------
// v transpose: vt[b][d][t] = v[(t*B+b)*D + d].  32x32 tiles.
// ---------------------------------------------------------------------------
__global__ __launch_bounds__(256)
void vt_kernel(const float* __restrict__ v, float* __restrict__ vt)
{
    __shared__ float tile[32][33];
    int b  = blockIdx.z;
    int t0 = blockIdx.x * 32;
    int d0 = blockIdx.y * 32;
    int x  = threadIdx.x & 31;
    int y  = threadIdx.x >> 5;
#pragma unroll
    for (int j = 0; j < 32; j += 8)
        tile[y + j][x] = v[((long)(t0 + y + j) * B_ + b) * D_ + d0 + x];
    __syncthreads();
#pragma unroll
    for (int j = 0; j < 32; j += 8)
        vt[(long)b * D_ * T_ + (long)(d0 + y + j) * T_ + t0 + x] = tile[x][y + j];
}

// ---------------------------------------------------------------------------
// Softmax over T for attention rows (in-place). mask: [B,T] bytes.
// ---------------------------------------------------------------------------
__global__ __launch_bounds__(256)
void attn_softmax_kernel(float* __restrict__ attn, const unsigned char* __restrict__ mask)
{
    int row = blockIdx.x;
    int b   = row & (B_ - 1);
    float* p = attn + (long)row * T_;
    const unsigned char* mrow = mask + (long)b * T_;
    int t = threadIdx.x;
    __shared__ float red[256];

    float x[4];
    float mx = -1e30f;
#pragma unroll
    for (int i = 0; i < 4; i++) {
        int tt = t + i * 256;
        float v = p[tt];
        if (mrow[tt]) v = -1e9f;
        x[i] = v;
        mx = fmaxf(mx, v);
    }
    red[t] = mx; __syncthreads();
    for (int s = 128; s > 0; s >>= 1) {
        if (t < s) red[t] = fmaxf(red[t], red[t + s]);
        __syncthreads();
    }
    mx = red[0]; __syncthreads();

    float sum = 0.f;
#pragma unroll
    for (int i = 0; i < 4; i++) { x[i] = fexp(x[i] - mx); sum += x[i]; }
    red[t] = sum; __syncthreads();
    for (int s = 128; s > 0; s >>= 1) {
        if (t < s) red[t] += red[t + s];
        __syncthreads();
    }
    float inv = 1.f / red[0];
#pragma unroll
    for (int i = 0; i < 4; i++) p[t + i * 256] = x[i] * inv;
}

// ---------------------------------------------------------------------------
// LayerNorm(outs + x). One block per row, D=512.
// ---------------------------------------------------------------------------
__global__ __launch_bounds__(256)
void ln_kernel(const float* __restrict__ outs, const float* __restrict__ x,
               const float* __restrict__ g, const float* __restrict__ bb,
               float* __restrict__ out)
{
    int row = blockIdx.x;
    int t = threadIdx.x;
    const float* o  = outs + (long)row * D_;
    const float* xr = x    + (long)row * D_;
    __shared__ float red[256];

    float v0 = o[t] + xr[t];
    float v1 = o[t + 256] + xr[t + 256];

    red[t] = v0 + v1; __syncthreads();
    for (int s = 128; s > 0; s >>= 1) { if (t < s) red[t] += red[t + s]; __syncthreads(); }
    float mu = red[0] * (1.f / D_); __syncthreads();

    float d0 = v0 - mu, d1 = v1 - mu;
    red[t] = d0 * d0 + d1 * d1; __syncthreads();
    for (int s = 128; s > 0; s >>= 1) { if (t < s) red[t] += red[t + s]; __syncthreads(); }
    float inv = rsqrtf(red[0] * (1.f / D_) + 1e-5f);

    out[(long)row * D_ + t]       = d0 * inv * g[t]       + bb[t];
    out[(long)row * D_ + t + 256] = d1 * inv * g[t + 256] + bb[t + 256];
}

// ---------------------------------------------------------------------------
// 2-way gate
// ---------------------------------------------------------------------------
__global__ __launch_bounds__(128)
void gates_kernel(const float* __restrict__ tok, const float* __restrict__ Wdiv,
                  const float* __restrict__ bdiv, float* __restrict__ gates)
{
    int row = blockIdx.x;
    int t = threadIdx.x;
    const float* x = tok + (long)row * D_;
    float z0 = 0.f, z1 = 0.f;
    for (int d = t; d < D_; d += 128) {
        float xv = x[d];
        z0 = fmaf(xv, Wdiv[d],      z0);
        z1 = fmaf(xv, Wdiv[D_ + d], z1);
    }
    __shared__ float r0[128], r1[128];
    r0[t] = z0; r1[t] = z1; __syncthreads();
    for (int s = 64; s > 0; s >>= 1) {
        if (t < s) { r0[t] += r0[t + s]; r1[t] += r1[t + s]; }
        __syncthreads();
    }
    if (t == 0) {
        float a = r0[0] + bdiv[0], b = r1[0] + bdiv[1];
        float m = fmaxf(a, b);
        float e0 = __expf(a - m), e1 = __expf(b - m);
        float inv = 1.f / (e0 + e1);
        gates[row * 2 + 0] = e0 * inv;
        gates[row * 2 + 1] = e1 * inv;
    }
}

// ---------------------------------------------------------------------------
// Log-prob base pass: out = coef[row] + z (no MUFU).
// ---------------------------------------------------------------------------
__global__ __launch_bounds__(256)
void lp_kernel(float* __restrict__ out, const float* __restrict__ coef)
{
    long i4 = (long)blockIdx.x * 256 + threadIdx.x;
    int row = (int)(i4 / (V_ / 4));
    float c = __ldg(coef + row);
    float4* p = (float4*)out + i4;
    float4 v = *p;
    v.x += c; v.y += c; v.z += c; v.w += c;
    *p = v;
}

// ---------------------------------------------------------------------------
// Copy-scatter in log space: ll <- log(exp(ll) + copy_val) via CAS.
// ---------------------------------------------------------------------------
__global__ __launch_bounds__(256)
void scatter_kernel(float* __restrict__ out, const float* __restrict__ attn,
                    const float* __restrict__ gates, const int* __restrict__ copy_seq)
{
    int gid = blockIdx.x * 256 + threadIdx.x;
    int row = gid >> 10;
    int t   = gid & 1023;
    int b   = row & (B_ - 1);
    float val = gates[row * 2 + 1] * attn[(long)row * T_ + t];
    int idx = copy_seq[t * B_ + b];
    int* ia = (int*)(out + (long)row * V_ + idx);

    int assumed = *ia;
    int old;
    do {
        old = assumed;
        float cur = __int_as_float(old);
        float nv = __logf(__expf(cur) + val);
        assumed = atomicCAS(ia, old, __float_as_int(nv));
    } while (assumed != old);
}

// ---------------------------------------------------------------------------
// Launch
// ---------------------------------------------------------------------------
extern "C" void kernel_launch(void* const* d_in, const int* in_sizes, int n_in,
                              void* d_out, int out_size)
{
    const float* outs = (const float*)d_in[0];
    const float* gs   = (const float*)d_in[1];
    const unsigned char* mask = (const unsigned char*)d_in[2];
    const int*   cseq = (const int*)d_in[3];
    const float* Wq = (const float*)d_in[4],  *bq = (const float*)d_in[5];
    const float* Wk = (const float*)d_in[6],  *bk = (const float*)d_in[7];
    const float* Wv = (const float*)d_in[8],  *bv = (const float*)d_in[9];
    const float* Wo = (const float*)d_in[10], *bo = (const float*)d_in[11];
    const float* lng = (const float*)d_in[12], *lnb = (const float*)d_in[13];
    const float* Wt = (const float*)d_in[14], *bt = (const float*)d_in[15];
    const float* Wgen = (const float*)d_in[16], *bgen = (const float*)d_in[17];
    const float* Wdiv = (const float*)d_in[18], *bdiv = (const float*)d_in[19];
    float* out = (float*)d_out;

    float* sc = nullptr;
    cudaGetSymbolAddress((void**)&sc, g_scratch);
    float* q     = sc + OQ;   // also reused as x after attention
    float* k     = sc + OK_;
    float* v     = sc + OV;
    float* vt    = sc + OVT;
    float* attn  = sc + OA;
    float* ctx   = sc + OC;
    float* ln    = sc + OL;
    float* tok   = sc + OT;
    float* gts   = sc + OG;
    float* coef  = sc + OM;
    float* rowsum = sc + ORS;
    __nv_bfloat16* wgen_b = (__nv_bfloat16*)(sc + OWB);
    __nv_bfloat16* tok_b  = (__nv_bfloat16*)(sc + OTB);

    const float scale = 0.044194173824159216f; // 1/sqrt(512)
    constexpr int SMEM = 65536;
    cudaFuncSetAttribute(mma_nt_kernel<0>, cudaFuncAttributeMaxDynamicSharedMemorySize, SMEM);
    cudaFuncSetAttribute(mma_nt_kernel<1>, cudaFuncAttributeMaxDynamicSharedMemorySize, SMEM);
    cudaFuncSetAttribute(mma_bf16_nt_kernel, cudaFuncAttributeMaxDynamicSharedMemorySize, SMEM);
    dim3 blk(256);

    // early: Wgen -> bf16, rowsum = 0
    f2b_kernel<<<(V_ * TS_ / 4 + 255) / 256, blk>>>((const float4*)Wgen, (__nv_bfloat162*)wgen_b, V_ * TS_ / 4);
    zero_kernel<<<SB / 256, blk>>>(rowsum);

    // q = (outs @ Wq^T + bq) * scale       [2048 x 512]
    mma_nt_kernel<0><<<dim3(4, 16, 1), blk, SMEM>>>(outs, Wq, bq, q, D_, D_, D_, D_, 0, 0, 0, scale);
    // k = gs @ Wk^T + bk                   [8192 x 512]
    mma_nt_kernel<0><<<dim3(4, 64, 1), blk, SMEM>>>(gs, Wk, bk, k, D_, D_, D_, D_, 0, 0, 0, 1.f);
    // v = gs @ Wv^T + bv
    mma_nt_kernel<0><<<dim3(4, 64, 1), blk, SMEM>>>(gs, Wv, bv, v, D_, D_, D_, D_, 0, 0, 0, 1.f);
    // v transpose for ctx GEMM
    vt_kernel<<<dim3(32, 16, 8), blk>>>(v, vt);
    // scores[s,b,t] = q[s,b,:] . k[t,b,:]  (batched over b)
    mma_nt_kernel<0><<<dim3(8, 2, 8), blk, SMEM>>>(q, k, nullptr, attn,
                                                   D_, B_ * D_, B_ * D_, B_ * T_,
                                                   D_, D_, T_, 1.f);
    // softmax over t (with mask)
    attn_softmax_kernel<<<SB, 256>>>(attn, mask);
    // ctx[s,b,:] = attn[s,b,:] @ v[:,b,:]   (NT vs v_T, batched over b)
    mma_nt_kernel<0><<<dim3(4, 2, 8), blk, SMEM>>>(attn, vt, nullptr, ctx,
                                                   T_, B_ * T_, T_, B_ * D_,
                                                   T_, (long)D_ * T_, D_, 1.f);
    // x = ctx @ Wo^T + bo   -> reuse q buffer
    mma_nt_kernel<0><<<dim3(4, 16, 1), blk, SMEM>>>(ctx, Wo, bo, q, D_, D_, D_, D_, 0, 0, 0, 1.f);
    // outs_ln = LN(outs + x)
    ln_kernel<<<SB, 256>>>(outs, q, lng, lnb, ln);
    // tok = tanh(outs_ln @ Wt^T + bt)
    mma_nt_kernel<1><<<dim3(4, 16, 1), blk, SMEM>>>(ln, Wt, bt, tok, D_, D_, D_, TS_, 0, 0, 0, 1.f);
    // gates
    gates_kernel<<<SB, 128>>>(tok, Wdiv, bdiv, gts);
    // tok -> bf16
    f2b_kernel<<<(SB * TS_ / 4 + 255) / 256, blk>>>((const float4*)tok, (__nv_bfloat162*)tok_b, SB * TS_ / 4);
    // logits = tok @ Wgen^T + bgen -> d_out; fused rowsum of exp(logits)
    mma_bf16_nt_kernel<<<dim3(250, 16, 1), blk, SMEM>>>(tok_b, wgen_b, bgen, out, rowsum,
                                                        TS_, TS_, TS_, V_);
    // coef = log(gen) - log(rowsum)
    coef_kernel<<<SB / 256, blk>>>(rowsum, gts, coef);
    // base log-probs in place
    lp_kernel<<<(SB * (V_ / 4)) / 256, 256>>>(out, coef);
    // copy scatter (log-space CAS merge)
    scatter_kernel<<<(SB * T_) / 256, 256>>>(out, attn, gts, cseq);
}